// round 13
// baseline (speedup 1.0000x reference)
#include <cuda_runtime.h>
#include <cuda_bf16.h>
#include <math.h>
#include <stdint.h>

// Problem constants
#define DMODEL   2048
#define NHEADS   32
#define NKVHEADS 8
#define HEADDIM  64
#define DKV      (NKVHEADS * HEADDIM)   // 512
#define SEQ_T    2048
#define ROWS_TOT 4096                    // b*T

// ---------------- scratch (no cudaMalloc allowed) ----------------
__device__ float g_Q[ROWS_TOT * DMODEL];
__device__ float g_K[ROWS_TOT * DKV];
__device__ float g_V[ROWS_TOT * DKV];
__device__ float g_Ctx[ROWS_TOT * DMODEL];
__device__ float g_cos[SEQ_T * 32];
__device__ float g_sin[SEQ_T * 32];

// bf16 hi/lo split scratch
__device__ __nv_bfloat16 g_xh[ROWS_TOT * DMODEL];
__device__ __nv_bfloat16 g_xl[ROWS_TOT * DMODEL];
__device__ __nv_bfloat16 g_ch[ROWS_TOT * DMODEL];
__device__ __nv_bfloat16 g_cl[ROWS_TOT * DMODEL];
// transposed weights [N, K] bf16 hi/lo
__device__ __nv_bfloat16 g_Wqh[DMODEL * DMODEL];
__device__ __nv_bfloat16 g_Wql[DMODEL * DMODEL];
__device__ __nv_bfloat16 g_Wkh[DKV * DMODEL];
__device__ __nv_bfloat16 g_Wkl[DKV * DMODEL];
__device__ __nv_bfloat16 g_Wvh[DKV * DMODEL];
__device__ __nv_bfloat16 g_Wvl[DKV * DMODEL];
__device__ __nv_bfloat16 g_Woh[DMODEL * DMODEL];
__device__ __nv_bfloat16 g_Wol[DMODEL * DMODEL];

// ================= small PTX helpers (sm_80-era, family-safe) ============
__device__ __forceinline__ uint32_t smem_u32(const void* p) {
    uint32_t a;
    asm("{ .reg .u64 t; cvta.to.shared.u64 t, %1; cvt.u32.u64 %0, t; }"
        : "=r"(a) : "l"(p));
    return a;
}
__device__ __forceinline__ void cp_async16(uint32_t dst, const void* src) {
    asm volatile("cp.async.cg.shared.global [%0], [%1], 16;"
                 :: "r"(dst), "l"(src) : "memory");
}
__device__ __forceinline__ void cp_commit() {
    asm volatile("cp.async.commit_group;" ::: "memory");
}
template <int N>
__device__ __forceinline__ void cp_wait() {
    asm volatile("cp.async.wait_group %0;" :: "n"(N) : "memory");
}
__device__ __forceinline__ void ldsm4(uint32_t* r, uint32_t addr) {
    asm volatile("ldmatrix.sync.aligned.m8n8.x4.shared.b16 {%0,%1,%2,%3}, [%4];"
                 : "=r"(r[0]), "=r"(r[1]), "=r"(r[2]), "=r"(r[3]) : "r"(addr));
}
__device__ __forceinline__ void mma16816(float* c, const uint32_t* a,
                                         uint32_t b0, uint32_t b1) {
    asm volatile(
        "mma.sync.aligned.m16n8k16.row.col.f32.bf16.bf16.f32 "
        "{%0,%1,%2,%3}, {%4,%5,%6,%7}, {%8,%9}, {%0,%1,%2,%3};"
        : "+f"(c[0]), "+f"(c[1]), "+f"(c[2]), "+f"(c[3])
        : "r"(a[0]), "r"(a[1]), "r"(a[2]), "r"(a[3]), "r"(b0), "r"(b1));
}

// ================= RoPE tables (accurate trig) =================
__global__ void rope_tables_kernel(float* __restrict__ cosT, float* __restrict__ sinT)
{
    int idx = blockIdx.x * blockDim.x + threadIdx.x;
    if (idx >= SEQ_T * 32) return;
    const int t = idx >> 5;
    const int i = idx & 31;
    const float inv = (float)pow(10000.0, -(double)(2 * i) / 64.0);
    const float ang = (float)t * inv;
    double s, c;
    sincos((double)ang, &s, &c);
    cosT[idx] = (float)c;
    sinT[idx] = (float)s;
}

// ================= fp32 -> bf16 hi/lo split =================
__global__ void split_hilo_kernel(const float* __restrict__ in,
                                  __nv_bfloat16* __restrict__ hi,
                                  __nv_bfloat16* __restrict__ lo, int n4)
{
    int idx = blockIdx.x * blockDim.x + threadIdx.x;
    if (idx >= n4) return;
    float4 v = ((const float4*)in)[idx];
    __nv_bfloat16 h[4], l[4];
    float vv[4] = {v.x, v.y, v.z, v.w};
#pragma unroll
    for (int i = 0; i < 4; i++) {
        h[i] = __float2bfloat16_rn(vv[i]);
        l[i] = __float2bfloat16_rn(vv[i] - __bfloat162float(h[i]));
    }
    ((uint64_t*)hi)[idx] = *(uint64_t*)h;
    ((uint64_t*)lo)[idx] = *(uint64_t*)l;
}

// ================= W [K,N] fp32 -> W^T [N,K] bf16 hi/lo ================
__global__ void splitT_kernel(const float* __restrict__ W,
                              __nv_bfloat16* __restrict__ Th,
                              __nv_bfloat16* __restrict__ Tl, int K, int N)
{
    __shared__ float tile[32][33];
    const int k0 = blockIdx.y * 32;
    const int n0 = blockIdx.x * 32;
    const int tx = threadIdx.x;   // 0..31
    const int ty = threadIdx.y;   // 0..7
#pragma unroll
    for (int r = ty; r < 32; r += 8)
        tile[r][tx] = W[(size_t)(k0 + r) * N + n0 + tx];
    __syncthreads();
#pragma unroll
    for (int r = ty; r < 32; r += 8) {
        float v = tile[tx][r];  // = W[k0+tx][n0+r]
        __nv_bfloat16 h = __float2bfloat16_rn(v);
        __nv_bfloat16 l = __float2bfloat16_rn(v - __bfloat162float(h));
        Th[(size_t)(n0 + r) * K + k0 + tx] = h;
        Tl[(size_t)(n0 + r) * K + k0 + tx] = l;
    }
}

// ================= HMMA split-bf16 GEMM ============================
// C[M,N] = (Ah+Al)[M,K] @ (Bh+Bl)[N,K]^T, fp32 accum, 3 MMA passes.
// CTA tile 128x128, BK=32, 256 threads (8 warps of 32x64).
// smem tiles: 128 rows x 32 bf16, row stride 80 B (pad -> conflict-free ldmatrix).
#define GROW_B   80
#define GTILE_B  (128 * GROW_B)          // 10240
#define GSTAGE_B (4 * GTILE_B)           // Ah, Al, Bh, Bl
#define GSMEM    (2 * GSTAGE_B)          // 81920

__global__ __launch_bounds__(256, 1) void gemm_mma(
    const __nv_bfloat16* __restrict__ Ah, const __nv_bfloat16* __restrict__ Al,
    const __nv_bfloat16* __restrict__ Bh, const __nv_bfloat16* __restrict__ Bl,
    const float* __restrict__ bias, float* __restrict__ C, int M, int N, int K)
{
    extern __shared__ char sm_raw[];
    const uint32_t sbase = smem_u32(sm_raw);
    const int tid = threadIdx.x;
    const int wid = tid >> 5;
    const int lid = tid & 31;
    const int m0 = blockIdx.y * 128;
    const int n0 = blockIdx.x * 128;
    const int wm = wid & 3;        // 0..3  -> 32-row band
    const int wn = wid >> 2;       // 0..1  -> 64-col band

    const __nv_bfloat16* srcs[4] = {
        Ah + (size_t)m0 * K, Al + (size_t)m0 * K,
        Bh + (size_t)n0 * K, Bl + (size_t)n0 * K };

    // load one stage (BK=32) with cp.async: 4 tiles x 512 16B-chunks
    auto load_stage = [&](int buf, int k0) {
        const uint32_t stage = sbase + buf * GSTAGE_B;
#pragma unroll
        for (int t = 0; t < 4; t++) {
            const __nv_bfloat16* src = srcs[t];
            const uint32_t dst = stage + t * GTILE_B;
#pragma unroll
            for (int it = 0; it < 2; it++) {
                const int c = it * 256 + tid;      // 0..511
                const int row = c >> 2;            // 0..127
                const int col = c & 3;             // 16B chunk
                cp_async16(dst + row * GROW_B + col * 16,
                           src + (size_t)row * K + k0 + col * 8);
            }
        }
    };

    float acc[2][8][4];
#pragma unroll
    for (int i = 0; i < 2; i++)
#pragma unroll
        for (int j = 0; j < 8; j++)
#pragma unroll
            for (int k = 0; k < 4; k++) acc[i][j][k] = 0.f;

    const int nch = K >> 5;     // chunks of 32
    load_stage(0, 0);  cp_commit();
    load_stage(1, 32); cp_commit();

    // per-lane ldmatrix address pieces
    const int lrow = lid & 15;          // row within 16-row group
    const int khalf = (lid >> 4) * 16;  // +16B for k8..15 quadrants

    for (int i = 0; i < nch; i++) {
        if (i >= nch - 2) { cp_wait<0>(); } else { cp_wait<1>(); }
        __syncthreads();

        const uint32_t stage = sbase + (i & 1) * GSTAGE_B;
        const uint32_t aHb = stage;
        const uint32_t aLb = stage + GTILE_B;
        const uint32_t bHb = stage + 2 * GTILE_B;
        const uint32_t bLb = stage + 3 * GTILE_B;

#pragma unroll
        for (int ks = 0; ks < 2; ks++) {
            const int kbyte = ks * 32 + khalf;

            uint32_t aH[2][4], aL[2][4], bH[4][4], bL[4][4];
#pragma unroll
            for (int mt = 0; mt < 2; mt++) {
                const uint32_t ro = (uint32_t)(wm * 32 + mt * 16 + lrow) * GROW_B + kbyte;
                ldsm4(aH[mt], aHb + ro);
                ldsm4(aL[mt], aLb + ro);
            }
#pragma unroll
            for (int nt = 0; nt < 4; nt++) {
                const uint32_t ro = (uint32_t)(wn * 64 + nt * 16 + lrow) * GROW_B + kbyte;
                ldsm4(bH[nt], bHb + ro);
                ldsm4(bL[nt], bLb + ro);
            }

#pragma unroll
            for (int mt = 0; mt < 2; mt++) {
#pragma unroll
                for (int nt = 0; nt < 4; nt++) {
                    // even n8 tile: regs {r0, r2}; odd: {r1, r3}
                    mma16816(acc[mt][2 * nt + 0], aH[mt], bH[nt][0], bH[nt][2]);
                    mma16816(acc[mt][2 * nt + 1], aH[mt], bH[nt][1], bH[nt][3]);
                    mma16816(acc[mt][2 * nt + 0], aH[mt], bL[nt][0], bL[nt][2]);
                    mma16816(acc[mt][2 * nt + 1], aH[mt], bL[nt][1], bL[nt][3]);
                    mma16816(acc[mt][2 * nt + 0], aL[mt], bH[nt][0], bH[nt][2]);
                    mma16816(acc[mt][2 * nt + 1], aL[mt], bH[nt][1], bH[nt][3]);
                }
            }
        }
        __syncthreads();
        if (i + 2 < nch) load_stage(i & 1, (i + 2) * 32);
        cp_commit();   // empty group when nothing issued; keeps wait-count bookkeeping simple
    }

    // epilogue: fragment layout c{0,1}=(m=lq,n=2lr+{0,1}), c{2,3}=(m+8, same n)
    const int lq = lid >> 2;
    const int lr = lid & 3;
#pragma unroll
    for (int mt = 0; mt < 2; mt++) {
#pragma unroll
        for (int nt8 = 0; nt8 < 8; nt8++) {
            const int m = m0 + wm * 32 + mt * 16 + lq;
            const int n = n0 + wn * 64 + nt8 * 8 + lr * 2;
            float b0 = 0.f, b1 = 0.f;
            if (bias) { b0 = bias[n]; b1 = bias[n + 1]; }
            float2 v0 = { acc[mt][nt8][0] + b0, acc[mt][nt8][1] + b1 };
            float2 v1 = { acc[mt][nt8][2] + b0, acc[mt][nt8][3] + b1 };
            *(float2*)&C[(size_t)m * N + n]       = v0;
            *(float2*)&C[(size_t)(m + 8) * N + n] = v1;
        }
    }
}

// ================= RoPE (in place, table-driven) =================
__global__ void rope_kernel(float* __restrict__ X,
                            const float* __restrict__ cosT,
                            const float* __restrict__ sinT,
                            int rows, int T, int width)
{
    const int pairsPerRow = width >> 1;
    const int total = rows * pairsPerRow;
    int idx = blockIdx.x * blockDim.x + threadIdx.x;
    if (idx >= total) return;

    const int row  = idx / pairsPerRow;
    const int p    = idx - row * pairsPerRow;
    const int head = p >> 5;
    const int i    = p & 31;
    const int t    = row % T;

    const float c = cosT[t * 32 + i];
    const float s = sinT[t * 32 + i];

    float* base = X + (size_t)row * width + head * 64;
    const float x1 = base[i];
    const float x2 = base[i + 32];
    base[i]      = x1 * c - x2 * s;
    base[i + 32] = x2 * c + x1 * s;
}

// ================= flash attention (fp32, causal, GQA) =================
#define ATT_PAD 4
#define ATT_LD  (64 + ATT_PAD)
#define ATT_SMEM (3 * 64 * ATT_LD * 4)

__global__ __launch_bounds__(256) void attn_kernel(
    const float* __restrict__ Q, const float* __restrict__ Kb,
    const float* __restrict__ Vb, float* __restrict__ O, int T)
{
    extern __shared__ float sm[];
    float (*sQ)[ATT_LD]  = (float(*)[ATT_LD])sm;
    float (*sKP)[ATT_LD] = (float(*)[ATT_LD])(sm + 64 * ATT_LD);
    float (*sV)[ATT_LD]  = (float(*)[ATT_LD])(sm + 2 * 64 * ATT_LD);

    const int tid = threadIdx.x;
    const int q0  = blockIdx.x * 64;
    const int h   = blockIdx.y;
    const int bz  = blockIdx.z;
    const int kvh = h >> 2;
    const float scale = 0.125f;

    const size_t qbase = ((size_t)bz * T) * DMODEL + (size_t)h * HEADDIM;
    const size_t kbase = ((size_t)bz * T) * DKV + (size_t)kvh * HEADDIM;

    for (int i = tid; i < 64 * 16; i += 256) {
        const int r = i >> 4, c4 = (i & 15) * 4;
        float4 v = *(const float4*)&Q[qbase + (size_t)(q0 + r) * DMODEL + c4];
        v.x *= scale; v.y *= scale; v.z *= scale; v.w *= scale;
        *(float4*)&sQ[r][c4] = v;
    }

    const int ty = tid >> 4, tx = tid & 15;
    const int r0 = ty * 4;

    float m[4], l[4], o[4][4];
#pragma unroll
    for (int i = 0; i < 4; i++) {
        m[i] = -1e30f; l[i] = 0.f;
#pragma unroll
        for (int j = 0; j < 4; j++) o[i][j] = 0.f;
    }

    const int nTiles = blockIdx.x + 1;
    for (int kt = 0; kt < nTiles; kt++) {
        const int s0 = kt * 64;

        __syncthreads();
        for (int i = tid; i < 64 * 16; i += 256) {
            const int r = i >> 4, c4 = (i & 15) * 4;
            *(float4*)&sKP[r][c4] = *(const float4*)&Kb[kbase + (size_t)(s0 + r) * DKV + c4];
            *(float4*)&sV[r][c4]  = *(const float4*)&Vb[kbase + (size_t)(s0 + r) * DKV + c4];
        }
        __syncthreads();

        float accS[4][4];
#pragma unroll
        for (int i = 0; i < 4; i++)
#pragma unroll
            for (int j = 0; j < 4; j++) accS[i][j] = 0.f;

#pragma unroll
        for (int d = 0; d < 64; d += 4) {
            float qv[4][4], kv[4][4];
#pragma unroll
            for (int i = 0; i < 4; i++) *(float4*)qv[i] = *(float4*)&sQ[r0 + i][d];
#pragma unroll
            for (int j = 0; j < 4; j++) *(float4*)kv[j] = *(float4*)&sKP[tx + 16 * j][d];
#pragma unroll
            for (int i = 0; i < 4; i++)
#pragma unroll
                for (int j = 0; j < 4; j++)
                    accS[i][j] += qv[i][0] * kv[j][0] + qv[i][1] * kv[j][1]
                                + qv[i][2] * kv[j][2] + qv[i][3] * kv[j][3];
        }

        if (kt == blockIdx.x) {
#pragma unroll
            for (int i = 0; i < 4; i++)
#pragma unroll
                for (int j = 0; j < 4; j++)
                    if (tx + 16 * j > r0 + i) accS[i][j] = -1e30f;
        }

        float rmax[4];
#pragma unroll
        for (int i = 0; i < 4; i++) {
            float v = fmaxf(fmaxf(accS[i][0], accS[i][1]), fmaxf(accS[i][2], accS[i][3]));
#pragma unroll
            for (int off = 8; off; off >>= 1)
                v = fmaxf(v, __shfl_xor_sync(0xffffffffu, v, off));
            rmax[i] = v;
        }

        __syncthreads();

#pragma unroll
        for (int i = 0; i < 4; i++) {
            const float mn   = fmaxf(m[i], rmax[i]);
            const float corr = __expf(m[i] - mn);
            float lsum = 0.f;
#pragma unroll
            for (int j = 0; j < 4; j++) {
                const float p = __expf(accS[i][j] - mn);
                sKP[r0 + i][tx + 16 * j] = p;
                lsum += p;
            }
#pragma unroll
            for (int off = 8; off; off >>= 1)
                lsum += __shfl_xor_sync(0xffffffffu, lsum, off);
            l[i] = l[i] * corr + lsum;
            m[i] = mn;
#pragma unroll
            for (int j = 0; j < 4; j++) o[i][j] *= corr;
        }
        __syncthreads();

#pragma unroll
        for (int s = 0; s < 64; s += 4) {
            float pv[4][4], vv[4][4];
#pragma unroll
            for (int i = 0; i < 4; i++) *(float4*)pv[i] = *(float4*)&sKP[r0 + i][s];
#pragma unroll
            for (int si = 0; si < 4; si++) *(float4*)vv[si] = *(float4*)&sV[s + si][tx * 4];
#pragma unroll
            for (int i = 0; i < 4; i++)
#pragma unroll
                for (int j = 0; j < 4; j++)
                    o[i][j] += pv[i][0] * vv[0][j] + pv[i][1] * vv[1][j]
                             + pv[i][2] * vv[2][j] + pv[i][3] * vv[3][j];
        }
    }

#pragma unroll
    for (int i = 0; i < 4; i++) {
        const float inv = 1.f / l[i];
        float4 v;
        v.x = o[i][0] * inv; v.y = o[i][1] * inv;
        v.z = o[i][2] * inv; v.w = o[i][3] * inv;
        *(float4*)&O[qbase + (size_t)(q0 + r0 + i) * DMODEL + tx * 4] = v;
    }
}

// ================= launch =================
extern "C" void kernel_launch(void* const* d_in, const int* in_sizes, int n_in,
                              void* d_out, int out_size)
{
    const float* x  = (const float*)d_in[0];
    const float* Wq = (const float*)d_in[1];
    const float* Wk = (const float*)d_in[2];
    const float* Wv = (const float*)d_in[3];
    const float* Wo = (const float*)d_in[4];
    const float* bo = (const float*)d_in[5];

    float *Q, *K, *V, *Ctx, *cosT, *sinT;
    __nv_bfloat16 *xh, *xl, *ch, *cl;
    __nv_bfloat16 *Wqh, *Wql, *Wkh, *Wkl, *Wvh, *Wvl, *Woh, *Wol;
    cudaGetSymbolAddress((void**)&Q,    g_Q);
    cudaGetSymbolAddress((void**)&K,    g_K);
    cudaGetSymbolAddress((void**)&V,    g_V);
    cudaGetSymbolAddress((void**)&Ctx,  g_Ctx);
    cudaGetSymbolAddress((void**)&cosT, g_cos);
    cudaGetSymbolAddress((void**)&sinT, g_sin);
    cudaGetSymbolAddress((void**)&xh,   g_xh);
    cudaGetSymbolAddress((void**)&xl,   g_xl);
    cudaGetSymbolAddress((void**)&ch,   g_ch);
    cudaGetSymbolAddress((void**)&cl,   g_cl);
    cudaGetSymbolAddress((void**)&Wqh,  g_Wqh);
    cudaGetSymbolAddress((void**)&Wql,  g_Wql);
    cudaGetSymbolAddress((void**)&Wkh,  g_Wkh);
    cudaGetSymbolAddress((void**)&Wkl,  g_Wkl);
    cudaGetSymbolAddress((void**)&Wvh,  g_Wvh);
    cudaGetSymbolAddress((void**)&Wvl,  g_Wvl);
    cudaGetSymbolAddress((void**)&Woh,  g_Woh);
    cudaGetSymbolAddress((void**)&Wol,  g_Wol);

    const int T = SEQ_T;
    const int rows = in_sizes[0] / DMODEL;   // 4096
    const int B = rows / T;                  // 2

    cudaFuncSetAttribute(gemm_mma,   cudaFuncAttributeMaxDynamicSharedMemorySize, GSMEM);
    cudaFuncSetAttribute(attn_kernel, cudaFuncAttributeMaxDynamicSharedMemorySize, ATT_SMEM);

    // RoPE tables
    rope_tables_kernel<<<(SEQ_T * 32 + 255) / 256, 256>>>(cosT, sinT);

    // split x into bf16 hi/lo
    {
        int n4 = rows * DMODEL / 4;
        split_hilo_kernel<<<(n4 + 255) / 256, 256>>>(x, xh, xl, n4);
    }
    // transpose + split weights
    splitT_kernel<<<dim3(DMODEL / 32, DMODEL / 32), dim3(32, 8)>>>(Wq, Wqh, Wql, DMODEL, DMODEL);
    splitT_kernel<<<dim3(DKV    / 32, DMODEL / 32), dim3(32, 8)>>>(Wk, Wkh, Wkl, DMODEL, DKV);
    splitT_kernel<<<dim3(DKV    / 32, DMODEL / 32), dim3(32, 8)>>>(Wv, Wvh, Wvl, DMODEL, DKV);
    splitT_kernel<<<dim3(DMODEL / 32, DMODEL / 32), dim3(32, 8)>>>(Wo, Woh, Wol, DMODEL, DMODEL);

    // QKV projections (HMMA tensor cores)
    gemm_mma<<<dim3(DMODEL / 128, rows / 128), 256, GSMEM>>>(xh, xl, Wqh, Wql, nullptr, Q, rows, DMODEL, DMODEL);
    gemm_mma<<<dim3(DKV    / 128, rows / 128), 256, GSMEM>>>(xh, xl, Wkh, Wkl, nullptr, K, rows, DKV,    DMODEL);
    gemm_mma<<<dim3(DKV    / 128, rows / 128), 256, GSMEM>>>(xh, xl, Wvh, Wvl, nullptr, V, rows, DKV,    DMODEL);

    // RoPE in place
    {
        int totQ = rows * (DMODEL / 2);
        int totK = rows * (DKV / 2);
        rope_kernel<<<(totQ + 255) / 256, 256>>>(Q, cosT, sinT, rows, T, DMODEL);
        rope_kernel<<<(totK + 255) / 256, 256>>>(K, cosT, sinT, rows, T, DKV);
    }

    // attention
    attn_kernel<<<dim3(T / 64, NHEADS, B), 256, ATT_SMEM>>>(Q, K, V, Ctx, T);

    // split ctx, then output projection (+bias)
    {
        int n4 = rows * DMODEL / 4;
        split_hilo_kernel<<<(n4 + 255) / 256, 256>>>(Ctx, ch, cl, n4);
    }
    gemm_mma<<<dim3(DMODEL / 128, rows / 128), 256, GSMEM>>>(ch, cl, Woh, Wol, bo, (float*)d_out, rows, DMODEL, DMODEL);
}

// round 14
// speedup vs baseline: 1.0048x; 1.0048x over previous
#include <cuda_runtime.h>
#include <cuda_bf16.h>
#include <math.h>
#include <stdint.h>

// Problem constants
#define DMODEL   2048
#define NHEADS   32
#define NKVHEADS 8
#define HEADDIM  64
#define DKV      (NKVHEADS * HEADDIM)   // 512
#define SEQ_T    2048
#define ROWS_TOT 4096                    // b*T

// ---------------- scratch (no cudaMalloc allowed) ----------------
__device__ float g_Q[ROWS_TOT * DMODEL];
__device__ float g_K[ROWS_TOT * DKV];
__device__ float g_V[ROWS_TOT * DKV];
__device__ float g_Ctx[ROWS_TOT * DMODEL];
__device__ float g_cos[SEQ_T * 32];
__device__ float g_sin[SEQ_T * 32];

// bf16 hi/lo split scratch
__device__ __nv_bfloat16 g_xh[ROWS_TOT * DMODEL];
__device__ __nv_bfloat16 g_xl[ROWS_TOT * DMODEL];
__device__ __nv_bfloat16 g_ch[ROWS_TOT * DMODEL];
__device__ __nv_bfloat16 g_cl[ROWS_TOT * DMODEL];
// transposed weights [N, K] bf16 hi/lo
__device__ __nv_bfloat16 g_Wqh[DMODEL * DMODEL];
__device__ __nv_bfloat16 g_Wql[DMODEL * DMODEL];
__device__ __nv_bfloat16 g_Wkh[DKV * DMODEL];
__device__ __nv_bfloat16 g_Wkl[DKV * DMODEL];
__device__ __nv_bfloat16 g_Wvh[DKV * DMODEL];
__device__ __nv_bfloat16 g_Wvl[DKV * DMODEL];
__device__ __nv_bfloat16 g_Woh[DMODEL * DMODEL];
__device__ __nv_bfloat16 g_Wol[DMODEL * DMODEL];

// ================= small PTX helpers (sm_80-era, family-safe) ============
__device__ __forceinline__ uint32_t smem_u32(const void* p) {
    uint32_t a;
    asm("{ .reg .u64 t; cvta.to.shared.u64 t, %1; cvt.u32.u64 %0, t; }"
        : "=r"(a) : "l"(p));
    return a;
}
__device__ __forceinline__ void cp_async16(uint32_t dst, const void* src) {
    asm volatile("cp.async.cg.shared.global [%0], [%1], 16;"
                 :: "r"(dst), "l"(src) : "memory");
}
__device__ __forceinline__ void cp_commit() {
    asm volatile("cp.async.commit_group;" ::: "memory");
}
template <int N>
__device__ __forceinline__ void cp_wait() {
    asm volatile("cp.async.wait_group %0;" :: "n"(N) : "memory");
}
__device__ __forceinline__ void ldsm4(uint32_t* r, uint32_t addr) {
    asm volatile("ldmatrix.sync.aligned.m8n8.x4.shared.b16 {%0,%1,%2,%3}, [%4];"
                 : "=r"(r[0]), "=r"(r[1]), "=r"(r[2]), "=r"(r[3]) : "r"(addr));
}
__device__ __forceinline__ void mma16816(float* c, const uint32_t* a,
                                         uint32_t b0, uint32_t b1) {
    asm volatile(
        "mma.sync.aligned.m16n8k16.row.col.f32.bf16.bf16.f32 "
        "{%0,%1,%2,%3}, {%4,%5,%6,%7}, {%8,%9}, {%0,%1,%2,%3};"
        : "+f"(c[0]), "+f"(c[1]), "+f"(c[2]), "+f"(c[3])
        : "r"(a[0]), "r"(a[1]), "r"(a[2]), "r"(a[3]), "r"(b0), "r"(b1));
}

// ================= RoPE tables (accurate trig) =================
__global__ void rope_tables_kernel(float* __restrict__ cosT, float* __restrict__ sinT)
{
    int idx = blockIdx.x * blockDim.x + threadIdx.x;
    if (idx >= SEQ_T * 32) return;
    const int t = idx >> 5;
    const int i = idx & 31;
    const float inv = (float)pow(10000.0, -(double)(2 * i) / 64.0);
    const float ang = (float)t * inv;
    double s, c;
    sincos((double)ang, &s, &c);
    cosT[idx] = (float)c;
    sinT[idx] = (float)s;
}

// ================= fp32 -> bf16 hi/lo split =================
__global__ void split_hilo_kernel(const float* __restrict__ in,
                                  __nv_bfloat16* __restrict__ hi,
                                  __nv_bfloat16* __restrict__ lo, int n4)
{
    int idx = blockIdx.x * blockDim.x + threadIdx.x;
    if (idx >= n4) return;
    float4 v = ((const float4*)in)[idx];
    __nv_bfloat16 h[4], l[4];
    float vv[4] = {v.x, v.y, v.z, v.w};
#pragma unroll
    for (int i = 0; i < 4; i++) {
        h[i] = __float2bfloat16_rn(vv[i]);
        l[i] = __float2bfloat16_rn(vv[i] - __bfloat162float(h[i]));
    }
    ((uint64_t*)hi)[idx] = *(uint64_t*)h;
    ((uint64_t*)lo)[idx] = *(uint64_t*)l;
}

// ================= W [K,N] fp32 -> W^T [N,K] bf16 hi/lo ================
__global__ void splitT_kernel(const float* __restrict__ W,
                              __nv_bfloat16* __restrict__ Th,
                              __nv_bfloat16* __restrict__ Tl, int K, int N)
{
    __shared__ float tile[32][33];
    const int k0 = blockIdx.y * 32;
    const int n0 = blockIdx.x * 32;
    const int tx = threadIdx.x;   // 0..31
    const int ty = threadIdx.y;   // 0..7
#pragma unroll
    for (int r = ty; r < 32; r += 8)
        tile[r][tx] = W[(size_t)(k0 + r) * N + n0 + tx];
    __syncthreads();
#pragma unroll
    for (int r = ty; r < 32; r += 8) {
        float v = tile[tx][r];  // = W[k0+tx][n0+r]
        __nv_bfloat16 h = __float2bfloat16_rn(v);
        __nv_bfloat16 l = __float2bfloat16_rn(v - __bfloat162float(h));
        Th[(size_t)(n0 + r) * K + k0 + tx] = h;
        Tl[(size_t)(n0 + r) * K + k0 + tx] = l;
    }
}

// ================= HMMA split-bf16 GEMM ============================
// C[M,N] = (Ah+Al)[M,K] @ (Bh+Bl)[N,K]^T, fp32 accum, 3 MMA passes.
// CTA tile 128x128, BK=32, 256 threads (8 warps of 32x64).
// smem tiles: 128 rows x 32 bf16, row stride 80 B (pad -> conflict-free ldmatrix).
#define GROW_B   80
#define GTILE_B  (128 * GROW_B)          // 10240
#define GSTAGE_B (4 * GTILE_B)           // Ah, Al, Bh, Bl
#define GSMEM    (2 * GSTAGE_B)          // 81920

__global__ __launch_bounds__(256, 1) void gemm_mma(
    const __nv_bfloat16* __restrict__ Ah, const __nv_bfloat16* __restrict__ Al,
    const __nv_bfloat16* __restrict__ Bh, const __nv_bfloat16* __restrict__ Bl,
    const float* __restrict__ bias, float* __restrict__ C, int M, int N, int K)
{
    extern __shared__ char sm_raw[];
    const uint32_t sbase = smem_u32(sm_raw);
    const int tid = threadIdx.x;
    const int wid = tid >> 5;
    const int lid = tid & 31;
    const int m0 = blockIdx.y * 128;
    const int n0 = blockIdx.x * 128;
    const int wm = wid & 3;        // 0..3  -> 32-row band
    const int wn = wid >> 2;       // 0..1  -> 64-col band

    const __nv_bfloat16* srcs[4] = {
        Ah + (size_t)m0 * K, Al + (size_t)m0 * K,
        Bh + (size_t)n0 * K, Bl + (size_t)n0 * K };

    // load one stage (BK=32) with cp.async: 4 tiles x 512 16B-chunks
    auto load_stage = [&](int buf, int k0) {
        const uint32_t stage = sbase + buf * GSTAGE_B;
#pragma unroll
        for (int t = 0; t < 4; t++) {
            const __nv_bfloat16* src = srcs[t];
            const uint32_t dst = stage + t * GTILE_B;
#pragma unroll
            for (int it = 0; it < 2; it++) {
                const int c = it * 256 + tid;      // 0..511
                const int row = c >> 2;            // 0..127
                const int col = c & 3;             // 16B chunk
                cp_async16(dst + row * GROW_B + col * 16,
                           src + (size_t)row * K + k0 + col * 8);
            }
        }
    };

    float acc[2][8][4];
#pragma unroll
    for (int i = 0; i < 2; i++)
#pragma unroll
        for (int j = 0; j < 8; j++)
#pragma unroll
            for (int k = 0; k < 4; k++) acc[i][j][k] = 0.f;

    const int nch = K >> 5;     // chunks of 32
    load_stage(0, 0);  cp_commit();
    load_stage(1, 32); cp_commit();

    // per-lane ldmatrix address pieces
    const int lrow = lid & 15;          // row within 16-row group
    const int khalf = (lid >> 4) * 16;  // +16B for k8..15 quadrants

    for (int i = 0; i < nch; i++) {
        if (i >= nch - 2) { cp_wait<0>(); } else { cp_wait<1>(); }
        __syncthreads();

        const uint32_t stage = sbase + (i & 1) * GSTAGE_B;
        const uint32_t aHb = stage;
        const uint32_t aLb = stage + GTILE_B;
        const uint32_t bHb = stage + 2 * GTILE_B;
        const uint32_t bLb = stage + 3 * GTILE_B;

#pragma unroll
        for (int ks = 0; ks < 2; ks++) {
            const int kbyte = ks * 32 + khalf;

            uint32_t aH[2][4], aL[2][4], bH[4][4], bL[4][4];
#pragma unroll
            for (int mt = 0; mt < 2; mt++) {
                const uint32_t ro = (uint32_t)(wm * 32 + mt * 16 + lrow) * GROW_B + kbyte;
                ldsm4(aH[mt], aHb + ro);
                ldsm4(aL[mt], aLb + ro);
            }
#pragma unroll
            for (int nt = 0; nt < 4; nt++) {
                const uint32_t ro = (uint32_t)(wn * 64 + nt * 16 + lrow) * GROW_B + kbyte;
                ldsm4(bH[nt], bHb + ro);
                ldsm4(bL[nt], bLb + ro);
            }

#pragma unroll
            for (int mt = 0; mt < 2; mt++) {
#pragma unroll
                for (int nt = 0; nt < 4; nt++) {
                    // even n8 tile: regs {r0, r2}; odd: {r1, r3}
                    mma16816(acc[mt][2 * nt + 0], aH[mt], bH[nt][0], bH[nt][2]);
                    mma16816(acc[mt][2 * nt + 1], aH[mt], bH[nt][1], bH[nt][3]);
                    mma16816(acc[mt][2 * nt + 0], aH[mt], bL[nt][0], bL[nt][2]);
                    mma16816(acc[mt][2 * nt + 1], aH[mt], bL[nt][1], bL[nt][3]);
                    mma16816(acc[mt][2 * nt + 0], aL[mt], bH[nt][0], bH[nt][2]);
                    mma16816(acc[mt][2 * nt + 1], aL[mt], bH[nt][1], bH[nt][3]);
                }
            }
        }
        __syncthreads();
        if (i + 2 < nch) load_stage(i & 1, (i + 2) * 32);
        cp_commit();   // empty group when nothing issued; keeps wait-count bookkeeping simple
    }

    // epilogue: fragment layout c{0,1}=(m=lq,n=2lr+{0,1}), c{2,3}=(m+8, same n)
    const int lq = lid >> 2;
    const int lr = lid & 3;
#pragma unroll
    for (int mt = 0; mt < 2; mt++) {
#pragma unroll
        for (int nt8 = 0; nt8 < 8; nt8++) {
            const int m = m0 + wm * 32 + mt * 16 + lq;
            const int n = n0 + wn * 64 + nt8 * 8 + lr * 2;
            float b0 = 0.f, b1 = 0.f;
            if (bias) { b0 = bias[n]; b1 = bias[n + 1]; }
            float2 v0 = { acc[mt][nt8][0] + b0, acc[mt][nt8][1] + b1 };
            float2 v1 = { acc[mt][nt8][2] + b0, acc[mt][nt8][3] + b1 };
            *(float2*)&C[(size_t)m * N + n]       = v0;
            *(float2*)&C[(size_t)(m + 8) * N + n] = v1;
        }
    }
}

// ================= RoPE (in place, table-driven) =================
__global__ void rope_kernel(float* __restrict__ X,
                            const float* __restrict__ cosT,
                            const float* __restrict__ sinT,
                            int rows, int T, int width)
{
    const int pairsPerRow = width >> 1;
    const int total = rows * pairsPerRow;
    int idx = blockIdx.x * blockDim.x + threadIdx.x;
    if (idx >= total) return;

    const int row  = idx / pairsPerRow;
    const int p    = idx - row * pairsPerRow;
    const int head = p >> 5;
    const int i    = p & 31;
    const int t    = row % T;

    const float c = cosT[t * 32 + i];
    const float s = sinT[t * 32 + i];

    float* base = X + (size_t)row * width + head * 64;
    const float x1 = base[i];
    const float x2 = base[i + 32];
    base[i]      = x1 * c - x2 * s;
    base[i + 32] = x2 * c + x1 * s;
}

// ================= flash attention (fp32, causal, GQA) =================
#define ATT_PAD 4
#define ATT_LD  (64 + ATT_PAD)
#define ATT_SMEM (3 * 64 * ATT_LD * 4)

__global__ __launch_bounds__(256) void attn_kernel(
    const float* __restrict__ Q, const float* __restrict__ Kb,
    const float* __restrict__ Vb, float* __restrict__ O, int T)
{
    extern __shared__ float sm[];
    float (*sQ)[ATT_LD]  = (float(*)[ATT_LD])sm;
    float (*sKP)[ATT_LD] = (float(*)[ATT_LD])(sm + 64 * ATT_LD);
    float (*sV)[ATT_LD]  = (float(*)[ATT_LD])(sm + 2 * 64 * ATT_LD);

    const int tid = threadIdx.x;
    const int q0  = blockIdx.x * 64;
    const int h   = blockIdx.y;
    const int bz  = blockIdx.z;
    const int kvh = h >> 2;
    const float scale = 0.125f;

    const size_t qbase = ((size_t)bz * T) * DMODEL + (size_t)h * HEADDIM;
    const size_t kbase = ((size_t)bz * T) * DKV + (size_t)kvh * HEADDIM;

    for (int i = tid; i < 64 * 16; i += 256) {
        const int r = i >> 4, c4 = (i & 15) * 4;
        float4 v = *(const float4*)&Q[qbase + (size_t)(q0 + r) * DMODEL + c4];
        v.x *= scale; v.y *= scale; v.z *= scale; v.w *= scale;
        *(float4*)&sQ[r][c4] = v;
    }

    const int ty = tid >> 4, tx = tid & 15;
    const int r0 = ty * 4;

    float m[4], l[4], o[4][4];
#pragma unroll
    for (int i = 0; i < 4; i++) {
        m[i] = -1e30f; l[i] = 0.f;
#pragma unroll
        for (int j = 0; j < 4; j++) o[i][j] = 0.f;
    }

    const int nTiles = blockIdx.x + 1;
    for (int kt = 0; kt < nTiles; kt++) {
        const int s0 = kt * 64;

        __syncthreads();
        for (int i = tid; i < 64 * 16; i += 256) {
            const int r = i >> 4, c4 = (i & 15) * 4;
            *(float4*)&sKP[r][c4] = *(const float4*)&Kb[kbase + (size_t)(s0 + r) * DKV + c4];
            *(float4*)&sV[r][c4]  = *(const float4*)&Vb[kbase + (size_t)(s0 + r) * DKV + c4];
        }
        __syncthreads();

        float accS[4][4];
#pragma unroll
        for (int i = 0; i < 4; i++)
#pragma unroll
            for (int j = 0; j < 4; j++) accS[i][j] = 0.f;

#pragma unroll
        for (int d = 0; d < 64; d += 4) {
            float qv[4][4], kv[4][4];
#pragma unroll
            for (int i = 0; i < 4; i++) *(float4*)qv[i] = *(float4*)&sQ[r0 + i][d];
#pragma unroll
            for (int j = 0; j < 4; j++) *(float4*)kv[j] = *(float4*)&sKP[tx + 16 * j][d];
#pragma unroll
            for (int i = 0; i < 4; i++)
#pragma unroll
                for (int j = 0; j < 4; j++)
                    accS[i][j] += qv[i][0] * kv[j][0] + qv[i][1] * kv[j][1]
                                + qv[i][2] * kv[j][2] + qv[i][3] * kv[j][3];
        }

        if (kt == blockIdx.x) {
#pragma unroll
            for (int i = 0; i < 4; i++)
#pragma unroll
                for (int j = 0; j < 4; j++)
                    if (tx + 16 * j > r0 + i) accS[i][j] = -1e30f;
        }

        float rmax[4];
#pragma unroll
        for (int i = 0; i < 4; i++) {
            float v = fmaxf(fmaxf(accS[i][0], accS[i][1]), fmaxf(accS[i][2], accS[i][3]));
#pragma unroll
            for (int off = 8; off; off >>= 1)
                v = fmaxf(v, __shfl_xor_sync(0xffffffffu, v, off));
            rmax[i] = v;
        }

        __syncthreads();

#pragma unroll
        for (int i = 0; i < 4; i++) {
            const float mn   = fmaxf(m[i], rmax[i]);
            const float corr = __expf(m[i] - mn);
            float lsum = 0.f;
#pragma unroll
            for (int j = 0; j < 4; j++) {
                const float p = __expf(accS[i][j] - mn);
                sKP[r0 + i][tx + 16 * j] = p;
                lsum += p;
            }
#pragma unroll
            for (int off = 8; off; off >>= 1)
                lsum += __shfl_xor_sync(0xffffffffu, lsum, off);
            l[i] = l[i] * corr + lsum;
            m[i] = mn;
#pragma unroll
            for (int j = 0; j < 4; j++) o[i][j] *= corr;
        }
        __syncthreads();

#pragma unroll
        for (int s = 0; s < 64; s += 4) {
            float pv[4][4], vv[4][4];
#pragma unroll
            for (int i = 0; i < 4; i++) *(float4*)pv[i] = *(float4*)&sKP[r0 + i][s];
#pragma unroll
            for (int si = 0; si < 4; si++) *(float4*)vv[si] = *(float4*)&sV[s + si][tx * 4];
#pragma unroll
            for (int i = 0; i < 4; i++)
#pragma unroll
                for (int j = 0; j < 4; j++)
                    o[i][j] += pv[i][0] * vv[0][j] + pv[i][1] * vv[1][j]
                             + pv[i][2] * vv[2][j] + pv[i][3] * vv[3][j];
        }
    }

#pragma unroll
    for (int i = 0; i < 4; i++) {
        const float inv = 1.f / l[i];
        float4 v;
        v.x = o[i][0] * inv; v.y = o[i][1] * inv;
        v.z = o[i][2] * inv; v.w = o[i][3] * inv;
        *(float4*)&O[qbase + (size_t)(q0 + r0 + i) * DMODEL + tx * 4] = v;
    }
}

// ================= launch =================
extern "C" void kernel_launch(void* const* d_in, const int* in_sizes, int n_in,
                              void* d_out, int out_size)
{
    const float* x  = (const float*)d_in[0];
    const float* Wq = (const float*)d_in[1];
    const float* Wk = (const float*)d_in[2];
    const float* Wv = (const float*)d_in[3];
    const float* Wo = (const float*)d_in[4];
    const float* bo = (const float*)d_in[5];

    float *Q, *K, *V, *Ctx, *cosT, *sinT;
    __nv_bfloat16 *xh, *xl, *ch, *cl;
    __nv_bfloat16 *Wqh, *Wql, *Wkh, *Wkl, *Wvh, *Wvl, *Woh, *Wol;
    cudaGetSymbolAddress((void**)&Q,    g_Q);
    cudaGetSymbolAddress((void**)&K,    g_K);
    cudaGetSymbolAddress((void**)&V,    g_V);
    cudaGetSymbolAddress((void**)&Ctx,  g_Ctx);
    cudaGetSymbolAddress((void**)&cosT, g_cos);
    cudaGetSymbolAddress((void**)&sinT, g_sin);
    cudaGetSymbolAddress((void**)&xh,   g_xh);
    cudaGetSymbolAddress((void**)&xl,   g_xl);
    cudaGetSymbolAddress((void**)&ch,   g_ch);
    cudaGetSymbolAddress((void**)&cl,   g_cl);
    cudaGetSymbolAddress((void**)&Wqh,  g_Wqh);
    cudaGetSymbolAddress((void**)&Wql,  g_Wql);
    cudaGetSymbolAddress((void**)&Wkh,  g_Wkh);
    cudaGetSymbolAddress((void**)&Wkl,  g_Wkl);
    cudaGetSymbolAddress((void**)&Wvh,  g_Wvh);
    cudaGetSymbolAddress((void**)&Wvl,  g_Wvl);
    cudaGetSymbolAddress((void**)&Woh,  g_Woh);
    cudaGetSymbolAddress((void**)&Wol,  g_Wol);

    const int T = SEQ_T;
    const int rows = in_sizes[0] / DMODEL;   // 4096
    const int B = rows / T;                  // 2

    cudaFuncSetAttribute(gemm_mma,   cudaFuncAttributeMaxDynamicSharedMemorySize, GSMEM);
    cudaFuncSetAttribute(attn_kernel, cudaFuncAttributeMaxDynamicSharedMemorySize, ATT_SMEM);

    // RoPE tables
    rope_tables_kernel<<<(SEQ_T * 32 + 255) / 256, 256>>>(cosT, sinT);

    // split x into bf16 hi/lo
    {
        int n4 = rows * DMODEL / 4;
        split_hilo_kernel<<<(n4 + 255) / 256, 256>>>(x, xh, xl, n4);
    }
    // transpose + split weights
    splitT_kernel<<<dim3(DMODEL / 32, DMODEL / 32), dim3(32, 8)>>>(Wq, Wqh, Wql, DMODEL, DMODEL);
    splitT_kernel<<<dim3(DKV    / 32, DMODEL / 32), dim3(32, 8)>>>(Wk, Wkh, Wkl, DMODEL, DKV);
    splitT_kernel<<<dim3(DKV    / 32, DMODEL / 32), dim3(32, 8)>>>(Wv, Wvh, Wvl, DMODEL, DKV);
    splitT_kernel<<<dim3(DMODEL / 32, DMODEL / 32), dim3(32, 8)>>>(Wo, Woh, Wol, DMODEL, DMODEL);

    // QKV projections (HMMA tensor cores)
    gemm_mma<<<dim3(DMODEL / 128, rows / 128), 256, GSMEM>>>(xh, xl, Wqh, Wql, nullptr, Q, rows, DMODEL, DMODEL);
    gemm_mma<<<dim3(DKV    / 128, rows / 128), 256, GSMEM>>>(xh, xl, Wkh, Wkl, nullptr, K, rows, DKV,    DMODEL);
    gemm_mma<<<dim3(DKV    / 128, rows / 128), 256, GSMEM>>>(xh, xl, Wvh, Wvl, nullptr, V, rows, DKV,    DMODEL);

    // RoPE in place
    {
        int totQ = rows * (DMODEL / 2);
        int totK = rows * (DKV / 2);
        rope_kernel<<<(totQ + 255) / 256, 256>>>(Q, cosT, sinT, rows, T, DMODEL);
        rope_kernel<<<(totK + 255) / 256, 256>>>(K, cosT, sinT, rows, T, DKV);
    }

    // attention
    attn_kernel<<<dim3(T / 64, NHEADS, B), 256, ATT_SMEM>>>(Q, K, V, Ctx, T);

    // split ctx, then output projection (+bias)
    {
        int n4 = rows * DMODEL / 4;
        split_hilo_kernel<<<(n4 + 255) / 256, 256>>>(Ctx, ch, cl, n4);
    }
    gemm_mma<<<dim3(DMODEL / 128, rows / 128), 256, GSMEM>>>(ch, cl, Woh, Wol, bo, (float*)d_out, rows, DMODEL, DMODEL);
}